// round 13
// baseline (speedup 1.0000x reference)
#include <cuda_runtime.h>
#include <cuda_fp16.h>
#include <cstdint>

#define T_LEN 1024
#define S_LEN 1024
#define BSZ 4
#define EMB 1024
#define NH 16
#define HD 64

// ---------------- scratch (device globals) ----------------------------------
__device__ __half g_q[4096 * 1024];                  // [m=t*4+b][f=h*64+d], scaled
__device__ __half g_k[4096 * 1024];                  // [m=s*4+b][f]
__device__ __half g_vth[64 * 64 * 1024];             // [z=(b,h)][d][s] (V transposed)
__device__ float  g_sc[(size_t)64 * 1024 * 1024];    // raw scores [z][t][s] (f32)
__device__ __half g_sch[(size_t)64 * 1024 * 1024];   // masked probs [z][t][s] (fp16)
__device__ __half g_ctx2[4096 * 1024];               // [m=t*4+b][e] (fp16)

// ============================================================================
__device__ __forceinline__ void mma16n8k16(float* c, const uint32_t* a, const uint32_t* b) {
    asm volatile(
        "mma.sync.aligned.m16n8k16.row.col.f32.f16.f16.f32 "
        "{%0,%1,%2,%3}, {%4,%5,%6,%7}, {%8,%9}, {%0,%1,%2,%3};"
        : "+f"(c[0]), "+f"(c[1]), "+f"(c[2]), "+f"(c[3])
        : "r"(a[0]), "r"(a[1]), "r"(a[2]), "r"(a[3]), "r"(b[0]), "r"(b[1]));
}
__device__ __forceinline__ uint32_t smem_u32(const void* p) {
    uint32_t a;
    asm("{ .reg .u64 t; cvta.to.shared.u64 t, %1; cvt.u32.u64 %0, t; }"
        : "=r"(a) : "l"(p));
    return a;
}
__device__ __forceinline__ void ldsm_x4(uint32_t* r, uint32_t addr) {
    asm volatile("ldmatrix.sync.aligned.m8n8.x4.shared.b16 {%0,%1,%2,%3}, [%4];"
        : "=r"(r[0]), "=r"(r[1]), "=r"(r[2]), "=r"(r[3]) : "r"(addr));
}

// ============================================================================
// fp16 NT GEMM, tile 128x64, 8 warps (4m x 2n), warp tile 32x32, BK=32 halfs,
// double buffered, ldmatrix fragment loads. Stride 40 halfs (LDSM-conflict-free).
//  MODE 0: Qproj  A=query f32, B=Wq f32   -> g_q fp16 ((v+b)*0.125)
//  MODE 1: KVproj A=key f32, B=Wkv f32    -> g_k fp16 / g_vth fp16 scatter
//  MODE 3: outproj A=g_ctx2 fp16, B=Wout f32 -> Cout f32 (+bias)
//  MODE 4: PV     A=g_sch[z] fp16, B=g_vth[z] fp16 -> g_ctx2 fp16
// ============================================================================
template<int MODE>
__global__ __launch_bounds__(256)
void gemm_h(const float* __restrict__ Af,
            const float* __restrict__ Bf,
            const float* __restrict__ bias,
            float* __restrict__ Cout)
{
    __shared__ __align__(16) __half As[2][128 * 40];
    __shared__ __align__(16) __half Bs[2][64 * 40];

    const int tid = threadIdx.x;
    const int wid = tid >> 5, lane = tid & 31;
    const int wm = wid & 3, wn = wid >> 2;
    const int g = lane >> 2, t4 = lane & 3;

    int m0, n0, z = 0, bq = 0, fq = 0;
    if constexpr (MODE == 4) {
        m0 = blockIdx.x * 128; n0 = 0; z = blockIdx.y;
        bq = z >> 4; fq = (z & 15) * 64;
    } else {
        m0 = blockIdx.y * 128; n0 = blockIdx.x * 64;
    }

    const __half* Ah = nullptr;
    const __half* Bh = nullptr;
    if constexpr (MODE == 3) Ah = g_ctx2;
    if constexpr (MODE == 4) {
        Ah = g_sch + (size_t)z * 1024 * 1024;
        Bh = g_vth + (size_t)z * 64 * 1024;
    }

    auto load_stage = [&](int s, int k0) {
        if constexpr (MODE == 0 || MODE == 1) {
            #pragma unroll
            for (int r = 0; r < 4; r++) {
                int idx = tid + r * 256;
                int row = idx >> 3, c4 = (idx & 7) * 4;
                float4 v = *(const float4*)(Af + (size_t)(m0 + row) * 1024 + k0 + c4);
                __half2 p0 = __floats2half2_rn(v.x, v.y);
                __half2 p1 = __floats2half2_rn(v.z, v.w);
                uint2 u = make_uint2(*(const uint32_t*)&p0, *(const uint32_t*)&p1);
                *(uint2*)&As[s][row * 40 + c4] = u;
            }
        } else {
            #pragma unroll
            for (int r = 0; r < 2; r++) {
                int idx = tid + r * 256;
                int row = idx >> 2, c8 = (idx & 3) * 8;
                uint4 u = *(const uint4*)(Ah + (size_t)(m0 + row) * 1024 + k0 + c8);
                *(uint4*)&As[s][row * 40 + c8] = u;
            }
        }
        if constexpr (MODE == 4) {
            int row = tid >> 2, c8 = (tid & 3) * 8;
            uint4 u = *(const uint4*)(Bh + (size_t)row * 1024 + k0 + c8);
            *(uint4*)&Bs[s][row * 40 + c8] = u;
        } else {
            #pragma unroll
            for (int r = 0; r < 2; r++) {
                int idx = tid + r * 256;
                int row = idx >> 3, c4 = (idx & 7) * 4;
                float4 v = *(const float4*)(Bf + (size_t)(n0 + row) * 1024 + k0 + c4);
                __half2 p0 = __floats2half2_rn(v.x, v.y);
                __half2 p1 = __floats2half2_rn(v.z, v.w);
                uint2 u = make_uint2(*(const uint32_t*)&p0, *(const uint32_t*)&p1);
                *(uint2*)&Bs[s][row * 40 + c4] = u;
            }
        }
    };

    // ldmatrix addresses (per stage)
    uint32_t aAddr[2], bAddr[2];
    {
        const int ar = wm * 32 + (lane & 15);
        const int ac = (lane >> 4) * 8;
        const int bn = wn * 32 + (lane & 7) + ((lane >> 4) * 8);
        const int bk = ((lane >> 3) & 1) * 8;
        #pragma unroll
        for (int s = 0; s < 2; s++) {
            aAddr[s] = smem_u32(&As[s][0]) + (uint32_t)(ar * 40 + ac) * 2;
            bAddr[s] = smem_u32(&Bs[s][0]) + (uint32_t)(bn * 40 + bk) * 2;
        }
    }

    float c[2][4][4];
    #pragma unroll
    for (int mi = 0; mi < 2; mi++)
        #pragma unroll
        for (int ni = 0; ni < 4; ni++)
            #pragma unroll
            for (int e = 0; e < 4; e++) c[mi][ni][e] = 0.f;

    load_stage(0, 0);
    __syncthreads();

    for (int i = 0; i < 32; i++) {
        int s = i & 1;
        #pragma unroll
        for (int ks = 0; ks < 2; ks++) {
            uint32_t a[2][4], bf[2][4];
            ldsm_x4(a[0], aAddr[s] + ks * 32);
            ldsm_x4(a[1], aAddr[s] + ks * 32 + 16 * 40 * 2);
            ldsm_x4(bf[0], bAddr[s] + ks * 32);
            ldsm_x4(bf[1], bAddr[s] + ks * 32 + 16 * 40 * 2);
            #pragma unroll
            for (int mi = 0; mi < 2; mi++)
                #pragma unroll
                for (int j = 0; j < 2; j++) {
                    mma16n8k16(c[mi][2 * j + 0], a[mi], &bf[j][0]);
                    mma16n8k16(c[mi][2 * j + 1], a[mi], &bf[j][2]);
                }
        }
        if (i + 1 < 32) {
            load_stage(s ^ 1, (i + 1) * 32);
            __syncthreads();
        }
    }

    // ---- epilogue
    #pragma unroll
    for (int mi = 0; mi < 2; mi++) {
        #pragma unroll
        for (int ni = 0; ni < 4; ni++) {
            int r0 = m0 + wm * 32 + mi * 16 + g;
            int col0 = n0 + wn * 32 + ni * 8 + t4 * 2;
            #pragma unroll
            for (int half_i = 0; half_i < 2; half_i++) {
                int row = r0 + half_i * 8;
                float v0 = c[mi][ni][half_i * 2 + 0];
                float v1 = c[mi][ni][half_i * 2 + 1];
                if constexpr (MODE == 0) {
                    v0 = (v0 + bias[col0]) * 0.125f;
                    v1 = (v1 + bias[col0 + 1]) * 0.125f;
                    __half2 h = __floats2half2_rn(v0, v1);
                    *(__half2*)&g_q[(size_t)row * 1024 + col0] = h;
                } else if constexpr (MODE == 1) {
                    v0 += bias[col0]; v1 += bias[col0 + 1];
                    if (col0 < 1024) {
                        __half2 h = __floats2half2_rn(v0, v1);
                        *(__half2*)&g_k[(size_t)row * 1024 + col0] = h;
                    } else {
                        int ff = col0 - 1024;
                        int h_ = ff >> 6, d = ff & 63;
                        int sI = row >> 2, bI = row & 3;
                        size_t base = (size_t)(((bI << 4) + h_) * 64 + d) * 1024 + sI;
                        g_vth[base] = __float2half_rn(v0);
                        g_vth[base + 1024] = __float2half_rn(v1);
                    }
                } else if constexpr (MODE == 3) {
                    float2 o = {v0 + bias[col0], v1 + bias[col0 + 1]};
                    *(float2*)&Cout[(size_t)row * 1024 + col0] = o;
                } else {
                    __half2 h = __floats2half2_rn(v0, v1);
                    *(__half2*)&g_ctx2[(size_t)(row * 4 + bq) * 1024 + fq + col0] = h;
                }
            }
        }
    }
}

// ============================================================================
// Scores GEMM fp16: per (s-blk, t-blk, z): 128x128 tile, K=64, one smem load.
// 8 warps (4m x 2n), warp tile 32x64, ldmatrix frags. Raw f32 scores -> g_sc.
// Stride 72 halfs = 144B (LDSM conflict-free).
// ============================================================================
__global__ __launch_bounds__(256)
void scores_gemm()
{
    __shared__ __align__(16) __half As[128 * 72];
    __shared__ __align__(16) __half Bs[128 * 72];

    const int tid = threadIdx.x;
    const int wid = tid >> 5, lane = tid & 31;
    const int wm = wid & 3, wn = wid >> 2;
    const int g = lane >> 2, t4 = lane & 3;
    const int s0b = blockIdx.x * 128;
    const int t0 = blockIdx.y * 128;
    const int z = blockIdx.z;
    const int b = z >> 4;
    const int fq = (z & 15) * 64;

    #pragma unroll
    for (int r = 0; r < 4; r++) {
        int idx = tid + r * 256;
        int row = idx >> 3, c8 = (idx & 7) * 8;
        uint4 ua = *(const uint4*)(g_q + (size_t)((t0 + row) * 4 + b) * 1024 + fq + c8);
        *(uint4*)&As[row * 72 + c8] = ua;
        uint4 ub = *(const uint4*)(g_k + (size_t)((s0b + row) * 4 + b) * 1024 + fq + c8);
        *(uint4*)&Bs[row * 72 + c8] = ub;
    }
    __syncthreads();

    uint32_t aAddr, bAddr;
    {
        const int ar = wm * 32 + (lane & 15);
        const int ac = (lane >> 4) * 8;
        const int bn = wn * 64 + (lane & 7) + ((lane >> 4) * 8);
        const int bk = ((lane >> 3) & 1) * 8;
        aAddr = smem_u32(&As[0]) + (uint32_t)(ar * 72 + ac) * 2;
        bAddr = smem_u32(&Bs[0]) + (uint32_t)(bn * 72 + bk) * 2;
    }

    float c[2][8][4];
    #pragma unroll
    for (int mi = 0; mi < 2; mi++)
        #pragma unroll
        for (int ni = 0; ni < 8; ni++)
            #pragma unroll
            for (int e = 0; e < 4; e++) c[mi][ni][e] = 0.f;

    #pragma unroll
    for (int ks = 0; ks < 4; ks++) {
        uint32_t a[2][4], bf[4][4];
        ldsm_x4(a[0], aAddr + ks * 32);
        ldsm_x4(a[1], aAddr + ks * 32 + 16 * 72 * 2);
        #pragma unroll
        for (int j = 0; j < 4; j++)
            ldsm_x4(bf[j], bAddr + ks * 32 + j * 16 * 72 * 2);
        #pragma unroll
        for (int mi = 0; mi < 2; mi++)
            #pragma unroll
            for (int j = 0; j < 4; j++) {
                mma16n8k16(c[mi][2 * j + 0], a[mi], &bf[j][0]);
                mma16n8k16(c[mi][2 * j + 1], a[mi], &bf[j][2]);
            }
    }

    float* out = g_sc + (size_t)z * (1024 * 1024);
    #pragma unroll
    for (int mi = 0; mi < 2; mi++) {
        #pragma unroll
        for (int ni = 0; ni < 8; ni++) {
            int r0 = t0 + wm * 32 + mi * 16 + g;
            int col0 = s0b + wn * 64 + ni * 8 + t4 * 2;
            float2 o0 = {c[mi][ni][0], c[mi][ni][1]};
            float2 o1 = {c[mi][ni][2], c[mi][ni][3]};
            *(float2*)&out[(size_t)r0 * 1024 + col0] = o0;
            *(float2*)&out[(size_t)(r0 + 8) * 1024 + col0] = o1;
        }
    }
}

// ============================================================================
// Softmax + mask + avg, block per (b,t): 16 warps = 16 heads, row in regs.
// probs -> g_sch (fp16); block-reduce over smem staging -> avg output.
// ============================================================================
__global__ __launch_bounds__(512)
void softmax_avg(const float* __restrict__ mask, float* __restrict__ avg_out)
{
    __shared__ __half st[16][1024];

    const int bt = blockIdx.x;              // b*1024 + t
    const int b = bt >> 10, t = bt & 1023;
    const int tid = threadIdx.x;
    const int wid = tid >> 5, lane = tid & 31;
    const int z = b * 16 + wid;

    const float4* rp = (const float4*)(g_sc + ((size_t)z * 1024 + t) * 1024) + lane;
    float4 x[8];
    #pragma unroll
    for (int i = 0; i < 8; i++) x[i] = rp[i * 32];

    float mx = -1e30f;
    #pragma unroll
    for (int i = 0; i < 8; i++)
        mx = fmaxf(mx, fmaxf(fmaxf(x[i].x, x[i].y), fmaxf(x[i].z, x[i].w)));
    #pragma unroll
    for (int o = 16; o >= 1; o >>= 1)
        mx = fmaxf(mx, __shfl_xor_sync(0xffffffffu, mx, o));

    float sum = 0.f;
    #pragma unroll
    for (int i = 0; i < 8; i++) {
        x[i].x = __expf(x[i].x - mx);
        x[i].y = __expf(x[i].y - mx);
        x[i].z = __expf(x[i].z - mx);
        x[i].w = __expf(x[i].w - mx);
        sum += (x[i].x + x[i].y) + (x[i].z + x[i].w);
    }
    #pragma unroll
    for (int o = 16; o >= 1; o >>= 1)
        sum += __shfl_xor_sync(0xffffffffu, sum, o);
    const float inv = 1.f / sum;

    const float4* mrow = (const float4*)(mask + (size_t)bt * 1024) + lane;
    __half* prow = g_sch + ((size_t)z * 1024 + t) * 1024;
    #pragma unroll
    for (int i = 0; i < 8; i++) {
        float4 mk = mrow[i * 32];
        float p0 = x[i].x * inv * mk.x;
        float p1 = x[i].y * inv * mk.y;
        float p2 = x[i].z * inv * mk.z;
        float p3 = x[i].w * inv * mk.w;
        __half2 q0 = __floats2half2_rn(p0, p1);
        __half2 q1 = __floats2half2_rn(p2, p3);
        uint2 u = make_uint2(*(const uint32_t*)&q0, *(const uint32_t*)&q1);
        int coff = lane * 4 + 128 * i;
        *(uint2*)&prow[coff] = u;
        *(uint2*)&st[wid][coff] = u;
    }
    __syncthreads();

    float s0 = 0.f, s1 = 0.f;
    #pragma unroll
    for (int h = 0; h < 16; h++) {
        __half2 hv = *(const __half2*)&st[h][tid * 2];
        float2 f = __half22float2(hv);
        s0 += f.x; s1 += f.y;
    }
    float2 o = {s0 * 0.0625f, s1 * 0.0625f};
    *(float2*)&avg_out[(size_t)bt * 1024 + tid * 2] = o;
}

// ---------------------------------------------------------------------------
extern "C" void kernel_launch(void* const* d_in, const int* in_sizes, int n_in,
                              void* d_out, int out_size)
{
    const float* query = (const float*)d_in[0];
    const float* key   = (const float*)d_in[1];
    const float* mask  = (const float*)d_in[2];
    const float* w_in  = (const float*)d_in[3];
    const float* b_in  = (const float*)d_in[4];
    const float* w_out = (const float*)d_in[5];
    const float* b_out = (const float*)d_in[6];
    float* out = (float*)d_out;                         // [t][b][e]
    float* avg = out + (size_t)T_LEN * BSZ * EMB;       // [b][t][s]

    // 1) Q projection -> g_q fp16 (scaled)
    gemm_h<0><<<dim3(16, 32), 256>>>(query, w_in, b_in, nullptr);
    // 2) KV projection -> g_k fp16, g_vth fp16 (V transposed)
    gemm_h<1><<<dim3(32, 32), 256>>>(key, w_in + EMB * EMB, b_in + EMB, nullptr);
    // 3) scores (raw f32) -> g_sc
    scores_gemm<<<dim3(8, 8, 64), 256>>>();
    // 4) softmax + mask + avg -> g_sch (fp16 probs), avg output
    softmax_avg<<<4096, 512>>>(mask, avg);
    // 5) PV -> g_ctx2 fp16 ([t,b,e])
    gemm_h<4><<<dim3(8, 64), 256>>>(nullptr, nullptr, nullptr, nullptr);
    // 6) output projection -> d_out (f32)
    gemm_h<3><<<dim3(16, 32), 256>>>(nullptr, w_out, b_out, out);
}

// round 14
// speedup vs baseline: 1.3096x; 1.3096x over previous
#include <cuda_runtime.h>
#include <cuda_fp16.h>
#include <cstdint>

#define T_LEN 1024
#define S_LEN 1024
#define BSZ 4
#define EMB 1024
#define NH 16
#define HD 64

// ---------------- scratch (device globals) ----------------------------------
__device__ __half g_q[4096 * 1024];                  // [m=t*4+b][f=h*64+d], scaled
__device__ __half g_k[4096 * 1024];                  // [m=s*4+b][f]
__device__ __half g_vth[64 * 64 * 1024];             // [z=(b,h)][d][s] (V transposed)
__device__ float  g_sc[(size_t)64 * 1024 * 1024];    // raw scores [z][t][s] (f32)
__device__ __half g_sch[(size_t)64 * 1024 * 1024];   // masked probs [z][t][s] (fp16)
__device__ __half g_ctx2[4096 * 1024];               // [m=t*4+b][e] (fp16)

// ============================================================================
__device__ __forceinline__ void mma16n8k16(float* c, const uint32_t* a, const uint32_t* b) {
    asm volatile(
        "mma.sync.aligned.m16n8k16.row.col.f32.f16.f16.f32 "
        "{%0,%1,%2,%3}, {%4,%5,%6,%7}, {%8,%9}, {%0,%1,%2,%3};"
        : "+f"(c[0]), "+f"(c[1]), "+f"(c[2]), "+f"(c[3])
        : "r"(a[0]), "r"(a[1]), "r"(a[2]), "r"(a[3]), "r"(b[0]), "r"(b[1]));
}

// ============================================================================
// fp16 NT GEMM, tile 128 x TN, 8 warps (4m x 2n), warp tile 32 x TN/2,
// BK=32 halfs, double buffered, scalar LDS fragment loads (stride 40 halfs).
//  MODE 0: Qproj  A=query f32, B=Wq f32      -> g_q fp16 ((v+b)*0.125)   TN=128
//  MODE 1: KVproj A=key f32, B=Wkv f32       -> g_k fp16 / g_vth scatter TN=128
//  MODE 3: outproj A=g_ctx2 fp16, B=Wout f32 -> Cout f32 (+bias)         TN=128
//  MODE 4: PV     A=g_sch[z] fp16, B=g_vth[z] fp16 -> g_ctx2 fp16        TN=64
// ============================================================================
template<int MODE, int TN>
__global__ __launch_bounds__(256)
void gemm_h(const float* __restrict__ Af,
            const float* __restrict__ Bf,
            const float* __restrict__ bias,
            float* __restrict__ Cout)
{
    constexpr int FN = TN / 16;     // n-frags per warp
    __shared__ __align__(16) __half As[2][128 * 40];
    __shared__ __align__(16) __half Bs[2][TN * 40];

    const int tid = threadIdx.x;
    const int wid = tid >> 5, lane = tid & 31;
    const int wm = wid & 3, wn = wid >> 2;
    const int g = lane >> 2, t4 = lane & 3;

    int m0, n0, z = 0, bq = 0, fq = 0;
    if constexpr (MODE == 4) {
        m0 = blockIdx.x * 128; n0 = 0; z = blockIdx.y;
        bq = z >> 4; fq = (z & 15) * 64;
    } else {
        m0 = blockIdx.y * 128; n0 = blockIdx.x * TN;
    }

    const __half* Ah = nullptr;
    const __half* Bh = nullptr;
    if constexpr (MODE == 3) Ah = g_ctx2;
    if constexpr (MODE == 4) {
        Ah = g_sch + (size_t)z * 1024 * 1024;
        Bh = g_vth + (size_t)z * 64 * 1024;
    }

    auto load_stage = [&](int s, int k0) {
        // ---- A tile 128 x 32
        if constexpr (MODE == 0 || MODE == 1) {
            #pragma unroll
            for (int r = 0; r < 4; r++) {
                int idx = tid + r * 256;
                int row = idx >> 3, c4 = (idx & 7) * 4;
                float4 v = *(const float4*)(Af + (size_t)(m0 + row) * 1024 + k0 + c4);
                __half2 p0 = __floats2half2_rn(v.x, v.y);
                __half2 p1 = __floats2half2_rn(v.z, v.w);
                uint2 u = make_uint2(*(const uint32_t*)&p0, *(const uint32_t*)&p1);
                *(uint2*)&As[s][row * 40 + c4] = u;
            }
        } else {
            #pragma unroll
            for (int r = 0; r < 2; r++) {
                int idx = tid + r * 256;
                int row = idx >> 2, c8 = (idx & 3) * 8;
                uint4 u = *(const uint4*)(Ah + (size_t)(m0 + row) * 1024 + k0 + c8);
                *(uint4*)&As[s][row * 40 + c8] = u;
            }
        }
        // ---- B tile TN x 32
        if constexpr (MODE == 4) {
            int row = tid >> 2, c8 = (tid & 3) * 8;
            uint4 u = *(const uint4*)(Bh + (size_t)row * 1024 + k0 + c8);
            *(uint4*)&Bs[s][row * 40 + c8] = u;
        } else {
            #pragma unroll
            for (int r = 0; r < TN / 32; r++) {
                int idx = tid + r * 256;
                int row = idx >> 3, c4 = (idx & 7) * 4;
                float4 v = *(const float4*)(Bf + (size_t)(n0 + row) * 1024 + k0 + c4);
                __half2 p0 = __floats2half2_rn(v.x, v.y);
                __half2 p1 = __floats2half2_rn(v.z, v.w);
                uint2 u = make_uint2(*(const uint32_t*)&p0, *(const uint32_t*)&p1);
                *(uint2*)&Bs[s][row * 40 + c4] = u;
            }
        }
    };

    float c[2][FN][4];
    #pragma unroll
    for (int mi = 0; mi < 2; mi++)
        #pragma unroll
        for (int ni = 0; ni < FN; ni++)
            #pragma unroll
            for (int e = 0; e < 4; e++) c[mi][ni][e] = 0.f;

    load_stage(0, 0);
    __syncthreads();

    for (int i = 0; i < 32; i++) {
        int s = i & 1;
        #pragma unroll
        for (int ks = 0; ks < 2; ks++) {
            const int kb = ks * 16 + t4 * 2;
            uint32_t a[2][4], bfr[FN][2];
            #pragma unroll
            for (int mi = 0; mi < 2; mi++) {
                int r = (wm * 32 + mi * 16 + g) * 40;
                a[mi][0] = *(const uint32_t*)&As[s][r + kb];
                a[mi][1] = *(const uint32_t*)&As[s][r + 320 + kb];
                a[mi][2] = *(const uint32_t*)&As[s][r + kb + 8];
                a[mi][3] = *(const uint32_t*)&As[s][r + 320 + kb + 8];
            }
            #pragma unroll
            for (int ni = 0; ni < FN; ni++) {
                int rn = (wn * (TN / 2) + ni * 8 + g) * 40;
                bfr[ni][0] = *(const uint32_t*)&Bs[s][rn + kb];
                bfr[ni][1] = *(const uint32_t*)&Bs[s][rn + kb + 8];
            }
            #pragma unroll
            for (int mi = 0; mi < 2; mi++)
                #pragma unroll
                for (int ni = 0; ni < FN; ni++)
                    mma16n8k16(c[mi][ni], a[mi], bfr[ni]);
        }
        if (i + 1 < 32) {
            load_stage(s ^ 1, (i + 1) * 32);
            __syncthreads();
        }
    }

    // ---- epilogue (pairs e0/e1 -> row, e2/e3 -> row+8; cols col0, col0+1)
    #pragma unroll
    for (int mi = 0; mi < 2; mi++) {
        #pragma unroll
        for (int ni = 0; ni < FN; ni++) {
            int r0 = m0 + wm * 32 + mi * 16 + g;
            int col0 = n0 + wn * (TN / 2) + ni * 8 + t4 * 2;
            #pragma unroll
            for (int half_i = 0; half_i < 2; half_i++) {
                int row = r0 + half_i * 8;
                float v0 = c[mi][ni][half_i * 2 + 0];
                float v1 = c[mi][ni][half_i * 2 + 1];
                if constexpr (MODE == 0) {
                    v0 = (v0 + bias[col0]) * 0.125f;
                    v1 = (v1 + bias[col0 + 1]) * 0.125f;
                    __half2 h = __floats2half2_rn(v0, v1);
                    *(__half2*)&g_q[(size_t)row * 1024 + col0] = h;
                } else if constexpr (MODE == 1) {
                    v0 += bias[col0]; v1 += bias[col0 + 1];
                    if (col0 < 1024) {
                        __half2 h = __floats2half2_rn(v0, v1);
                        *(__half2*)&g_k[(size_t)row * 1024 + col0] = h;
                    } else {
                        int ff = col0 - 1024;
                        int h_ = ff >> 6, d = ff & 63;
                        int sI = row >> 2, bI = row & 3;
                        size_t base = (size_t)(((bI << 4) + h_) * 64 + d) * 1024 + sI;
                        g_vth[base] = __float2half_rn(v0);
                        g_vth[base + 1024] = __float2half_rn(v1);
                    }
                } else if constexpr (MODE == 3) {
                    float2 o = {v0 + bias[col0], v1 + bias[col0 + 1]};
                    *(float2*)&Cout[(size_t)row * 1024 + col0] = o;
                } else {  // MODE 4: ctx -> [t,b,e] fp16
                    __half2 h = __floats2half2_rn(v0, v1);
                    *(__half2*)&g_ctx2[(size_t)(row * 4 + bq) * 1024 + fq + col0] = h;
                }
            }
        }
    }
}

// ============================================================================
// Scores GEMM fp16: per (s-blk, t-blk, z): 128x128 tile, K=64 (one load, no
// double buffer). 8 warps (4m x 2n), warp tile 32x64. Raw f32 scores -> g_sc.
// ============================================================================
__global__ __launch_bounds__(256)
void scores_gemm()
{
    __shared__ __align__(16) __half As[128 * 72];
    __shared__ __align__(16) __half Bs[128 * 72];

    const int tid = threadIdx.x;
    const int wid = tid >> 5, lane = tid & 31;
    const int wm = wid & 3, wn = wid >> 2;
    const int g = lane >> 2, t4 = lane & 3;
    const int s0b = blockIdx.x * 128;
    const int t0 = blockIdx.y * 128;
    const int z = blockIdx.z;
    const int b = z >> 4;
    const int fq = (z & 15) * 64;

    #pragma unroll
    for (int r = 0; r < 4; r++) {
        int idx = tid + r * 256;
        int row = idx >> 3, c8 = (idx & 7) * 8;
        uint4 ua = *(const uint4*)(g_q + (size_t)((t0 + row) * 4 + b) * 1024 + fq + c8);
        *(uint4*)&As[row * 72 + c8] = ua;
        uint4 ub = *(const uint4*)(g_k + (size_t)((s0b + row) * 4 + b) * 1024 + fq + c8);
        *(uint4*)&Bs[row * 72 + c8] = ub;
    }
    __syncthreads();

    float c[2][8][4];
    #pragma unroll
    for (int mi = 0; mi < 2; mi++)
        #pragma unroll
        for (int ni = 0; ni < 8; ni++)
            #pragma unroll
            for (int e = 0; e < 4; e++) c[mi][ni][e] = 0.f;

    #pragma unroll
    for (int step = 0; step < 4; step++) {
        const int kb = step * 16 + t4 * 2;
        uint32_t a[2][4], bfr[8][2];
        #pragma unroll
        for (int mi = 0; mi < 2; mi++) {
            int r = (wm * 32 + mi * 16 + g) * 72;
            a[mi][0] = *(const uint32_t*)&As[r + kb];
            a[mi][1] = *(const uint32_t*)&As[r + 576 + kb];
            a[mi][2] = *(const uint32_t*)&As[r + kb + 8];
            a[mi][3] = *(const uint32_t*)&As[r + 576 + kb + 8];
        }
        #pragma unroll
        for (int ni = 0; ni < 8; ni++) {
            int rn = (wn * 64 + ni * 8 + g) * 72;
            bfr[ni][0] = *(const uint32_t*)&Bs[rn + kb];
            bfr[ni][1] = *(const uint32_t*)&Bs[rn + kb + 8];
        }
        #pragma unroll
        for (int mi = 0; mi < 2; mi++)
            #pragma unroll
            for (int ni = 0; ni < 8; ni++)
                mma16n8k16(c[mi][ni], a[mi], bfr[ni]);
    }

    float* out = g_sc + (size_t)z * (1024 * 1024);
    #pragma unroll
    for (int mi = 0; mi < 2; mi++) {
        #pragma unroll
        for (int ni = 0; ni < 8; ni++) {
            int r0 = t0 + wm * 32 + mi * 16 + g;
            int col0 = s0b + wn * 64 + ni * 8 + t4 * 2;
            float2 o0 = {c[mi][ni][0], c[mi][ni][1]};
            float2 o1 = {c[mi][ni][2], c[mi][ni][3]};
            *(float2*)&out[(size_t)r0 * 1024 + col0] = o0;
            *(float2*)&out[(size_t)(r0 + 8) * 1024 + col0] = o1;
        }
    }
}

// ============================================================================
// Softmax + mask + avg, block per (b,t): 16 warps = 16 heads, row in regs.
// probs -> g_sch (fp16); block-reduce over smem staging -> avg output.
// ============================================================================
__global__ __launch_bounds__(512)
void softmax_avg(const float* __restrict__ mask, float* __restrict__ avg_out)
{
    __shared__ __half st[16][1024];

    const int bt = blockIdx.x;              // b*1024 + t
    const int b = bt >> 10, t = bt & 1023;
    const int tid = threadIdx.x;
    const int wid = tid >> 5, lane = tid & 31;
    const int z = b * 16 + wid;

    const float4* rp = (const float4*)(g_sc + ((size_t)z * 1024 + t) * 1024) + lane;
    float4 x[8];
    #pragma unroll
    for (int i = 0; i < 8; i++) x[i] = rp[i * 32];

    float mx = -1e30f;
    #pragma unroll
    for (int i = 0; i < 8; i++)
        mx = fmaxf(mx, fmaxf(fmaxf(x[i].x, x[i].y), fmaxf(x[i].z, x[i].w)));
    #pragma unroll
    for (int o = 16; o >= 1; o >>= 1)
        mx = fmaxf(mx, __shfl_xor_sync(0xffffffffu, mx, o));

    float sum = 0.f;
    #pragma unroll
    for (int i = 0; i < 8; i++) {
        x[i].x = __expf(x[i].x - mx);
        x[i].y = __expf(x[i].y - mx);
        x[i].z = __expf(x[i].z - mx);
        x[i].w = __expf(x[i].w - mx);
        sum += (x[i].x + x[i].y) + (x[i].z + x[i].w);
    }
    #pragma unroll
    for (int o = 16; o >= 1; o >>= 1)
        sum += __shfl_xor_sync(0xffffffffu, sum, o);
    const float inv = 1.f / sum;

    const float4* mrow = (const float4*)(mask + (size_t)bt * 1024) + lane;
    __half* prow = g_sch + ((size_t)z * 1024 + t) * 1024;
    #pragma unroll
    for (int i = 0; i < 8; i++) {
        float4 mk = mrow[i * 32];
        float p0 = x[i].x * inv * mk.x;
        float p1 = x[i].y * inv * mk.y;
        float p2 = x[i].z * inv * mk.z;
        float p3 = x[i].w * inv * mk.w;
        __half2 q0 = __floats2half2_rn(p0, p1);
        __half2 q1 = __floats2half2_rn(p2, p3);
        uint2 u = make_uint2(*(const uint32_t*)&q0, *(const uint32_t*)&q1);
        int coff = lane * 4 + 128 * i;
        *(uint2*)&prow[coff] = u;
        *(uint2*)&st[wid][coff] = u;
    }
    __syncthreads();

    float s0 = 0.f, s1 = 0.f;
    #pragma unroll
    for (int h = 0; h < 16; h++) {
        __half2 hv = *(const __half2*)&st[h][tid * 2];
        float2 f = __half22float2(hv);
        s0 += f.x; s1 += f.y;
    }
    float2 o = {s0 * 0.0625f, s1 * 0.0625f};
    *(float2*)&avg_out[(size_t)bt * 1024 + tid * 2] = o;
}

// ---------------------------------------------------------------------------
extern "C" void kernel_launch(void* const* d_in, const int* in_sizes, int n_in,
                              void* d_out, int out_size)
{
    const float* query = (const float*)d_in[0];
    const float* key   = (const float*)d_in[1];
    const float* mask  = (const float*)d_in[2];
    const float* w_in  = (const float*)d_in[3];
    const float* b_in  = (const float*)d_in[4];
    const float* w_out = (const float*)d_in[5];
    const float* b_out = (const float*)d_in[6];
    float* out = (float*)d_out;                         // [t][b][e]
    float* avg = out + (size_t)T_LEN * BSZ * EMB;       // [b][t][s]

    // 1) Q projection -> g_q fp16 (scaled), 128x128 tiles
    gemm_h<0, 128><<<dim3(8, 32), 256>>>(query, w_in, b_in, nullptr);
    // 2) KV projection -> g_k fp16, g_vth fp16 (V transposed), 128x128 tiles
    gemm_h<1, 128><<<dim3(16, 32), 256>>>(key, w_in + EMB * EMB, b_in + EMB, nullptr);
    // 3) scores (raw f32) -> g_sc
    scores_gemm<<<dim3(8, 8, 64), 256>>>();
    // 4) softmax + mask + avg -> g_sch (fp16 probs), avg output
    softmax_avg<<<4096, 512>>>(mask, avg);
    // 5) PV -> g_ctx2 fp16 ([t,b,e]), 128x64 tiles
    gemm_h<4, 64><<<dim3(8, 64), 256>>>(nullptr, nullptr, nullptr, nullptr);
    // 6) output projection -> d_out (f32), 128x128 tiles
    gemm_h<3, 128><<<dim3(8, 32), 256>>>(nullptr, w_out, b_out, out);
}

// round 17
// speedup vs baseline: 1.3573x; 1.0364x over previous
#include <cuda_runtime.h>
#include <cuda_fp16.h>
#include <cstdint>

#define T_LEN 1024
#define S_LEN 1024
#define BSZ 4
#define EMB 1024
#define NH 16
#define HD 64

// ---------------- scratch (device globals) ----------------------------------
__device__ __half g_qf[4096 * 1024];                 // query fp16 [t*4+b][e]
__device__ __half g_kf[4096 * 1024];                 // key   fp16 [s*4+b][e]
__device__ __half g_wi[2048 * 1024 + 1024 * 1024];   // w_in  fp16 [3072][1024]
__device__ __half g_wo[1024 * 1024];                 // w_out fp16 [1024][1024]
__device__ __half g_q[4096 * 1024];                  // [m=t*4+b][f=h*64+d], scaled
__device__ __half g_k[4096 * 1024];                  // [m=s*4+b][f]
__device__ __half g_vth[64 * 64 * 1024];             // [z=(b,h)][d][s] (V transposed)
__device__ float  g_sc[(size_t)64 * 1024 * 1024];    // raw scores [z][t][s] (f32)
__device__ __half g_sch[(size_t)64 * 1024 * 1024];   // masked probs [z][t][s] (fp16)
__device__ __half g_ctx2[4096 * 1024];               // [m=t*4+b][e] (fp16)

// ============================================================================
__device__ __forceinline__ void mma16n8k16(float* c, const uint32_t* a, const uint32_t* b) {
    asm volatile(
        "mma.sync.aligned.m16n8k16.row.col.f32.f16.f16.f32 "
        "{%0,%1,%2,%3}, {%4,%5,%6,%7}, {%8,%9}, {%0,%1,%2,%3};"
        : "+f"(c[0]), "+f"(c[1]), "+f"(c[2]), "+f"(c[3])
        : "r"(a[0]), "r"(a[1]), "r"(a[2]), "r"(a[3]), "r"(b[0]), "r"(b[1]));
}

// ============================================================================
// f32 -> fp16 conversion (vectorized, grid-stride)
// ============================================================================
__global__ __launch_bounds__(256)
void cvt_f2h(const float* __restrict__ src, __half* __restrict__ dst, int n4)
{
    int i = blockIdx.x * 256 + threadIdx.x;
    if (i < n4) {
        float4 v = ((const float4*)src)[i];
        __half2 p0 = __floats2half2_rn(v.x, v.y);
        __half2 p1 = __floats2half2_rn(v.z, v.w);
        uint2 u = make_uint2(*(const uint32_t*)&p0, *(const uint32_t*)&p1);
        ((uint2*)dst)[i] = u;
    }
}

// ============================================================================
// fp16 NT GEMM, tile 128 x TN, 8 warps (4m x 2n), warp tile 32 x TN/2,
// BK=32 halfs, double buffered, scalar LDS frag loads (stride 40 halfs).
// All operands fp16 in gmem (uint4 loads).
//  MODE 0: Qproj  A=g_qf, B=g_wi[0:1024]    -> g_q ((v+b)*0.125)     TN=128
//  MODE 1: KVproj A=g_kf, B=g_wi[1024:3072] -> g_k / g_vth scatter   TN=128
//  MODE 3: outproj A=g_ctx2, B=g_wo         -> Cout f32 (+bias)      TN=128
//  MODE 4: PV     A=g_sch[z], B=g_vth[z]    -> g_ctx2 fp16           TN=64
// ============================================================================
template<int MODE, int TN>
__global__ __launch_bounds__(256)
void gemm_h(const float* __restrict__ bias, float* __restrict__ Cout)
{
    constexpr int FN = TN / 16;
    __shared__ __align__(16) __half As[2][128 * 40];
    __shared__ __align__(16) __half Bs[2][TN * 40];

    const int tid = threadIdx.x;
    const int wid = tid >> 5, lane = tid & 31;
    const int wm = wid & 3, wn = wid >> 2;
    const int g = lane >> 2, t4 = lane & 3;

    int m0, n0, z = 0, bq = 0, fq = 0;
    if constexpr (MODE == 4) {
        m0 = blockIdx.x * 128; n0 = 0; z = blockIdx.y;
        bq = z >> 4; fq = (z & 15) * 64;
    } else {
        m0 = blockIdx.y * 128; n0 = blockIdx.x * TN;
    }

    const __half* Ah;
    const __half* Bh;
    if constexpr (MODE == 0)      { Ah = g_qf;   Bh = g_wi; }
    else if constexpr (MODE == 1) { Ah = g_kf;   Bh = g_wi + (size_t)1024 * 1024; }
    else if constexpr (MODE == 3) { Ah = g_ctx2; Bh = g_wo; }
    else {
        Ah = g_sch + (size_t)z * 1024 * 1024;
        Bh = g_vth + (size_t)z * 64 * 1024;
    }

    auto load_stage = [&](int s, int k0) {
        #pragma unroll
        for (int r = 0; r < 2; r++) {
            int idx = tid + r * 256;
            int row = idx >> 2, c8 = (idx & 3) * 8;
            uint4 u = *(const uint4*)(Ah + (size_t)(m0 + row) * 1024 + k0 + c8);
            *(uint4*)&As[s][row * 40 + c8] = u;
        }
        #pragma unroll
        for (int r = 0; r < TN / 64; r++) {
            int idx = tid + r * 256;
            int row = idx >> 2, c8 = (idx & 3) * 8;
            uint4 u = *(const uint4*)(Bh + (size_t)(n0 + row) * 1024 + k0 + c8);
            *(uint4*)&Bs[s][row * 40 + c8] = u;
        }
    };

    float c[2][FN][4];
    #pragma unroll
    for (int mi = 0; mi < 2; mi++)
        #pragma unroll
        for (int ni = 0; ni < FN; ni++)
            #pragma unroll
            for (int e = 0; e < 4; e++) c[mi][ni][e] = 0.f;

    load_stage(0, 0);
    __syncthreads();

    for (int i = 0; i < 32; i++) {
        int s = i & 1;
        #pragma unroll
        for (int ks = 0; ks < 2; ks++) {
            const int kb = ks * 16 + t4 * 2;
            uint32_t a[2][4], bfr[FN][2];
            #pragma unroll
            for (int mi = 0; mi < 2; mi++) {
                int r = (wm * 32 + mi * 16 + g) * 40;
                a[mi][0] = *(const uint32_t*)&As[s][r + kb];
                a[mi][1] = *(const uint32_t*)&As[s][r + 320 + kb];
                a[mi][2] = *(const uint32_t*)&As[s][r + kb + 8];
                a[mi][3] = *(const uint32_t*)&As[s][r + 320 + kb + 8];
            }
            #pragma unroll
            for (int ni = 0; ni < FN; ni++) {
                int rn = (wn * (TN / 2) + ni * 8 + g) * 40;
                bfr[ni][0] = *(const uint32_t*)&Bs[s][rn + kb];
                bfr[ni][1] = *(const uint32_t*)&Bs[s][rn + kb + 8];
            }
            #pragma unroll
            for (int mi = 0; mi < 2; mi++)
                #pragma unroll
                for (int ni = 0; ni < FN; ni++)
                    mma16n8k16(c[mi][ni], a[mi], bfr[ni]);
        }
        if (i + 1 < 32) {
            load_stage(s ^ 1, (i + 1) * 32);
            __syncthreads();
        }
    }

    // ---- epilogue
    #pragma unroll
    for (int mi = 0; mi < 2; mi++) {
        #pragma unroll
        for (int ni = 0; ni < FN; ni++) {
            int r0 = m0 + wm * 32 + mi * 16 + g;
            int col0 = n0 + wn * (TN / 2) + ni * 8 + t4 * 2;
            #pragma unroll
            for (int half_i = 0; half_i < 2; half_i++) {
                int row = r0 + half_i * 8;
                float v0 = c[mi][ni][half_i * 2 + 0];
                float v1 = c[mi][ni][half_i * 2 + 1];
                if constexpr (MODE == 0) {
                    v0 = (v0 + bias[col0]) * 0.125f;
                    v1 = (v1 + bias[col0 + 1]) * 0.125f;
                    __half2 h = __floats2half2_rn(v0, v1);
                    *(__half2*)&g_q[(size_t)row * 1024 + col0] = h;
                } else if constexpr (MODE == 1) {
                    v0 += bias[col0]; v1 += bias[col0 + 1];
                    if (col0 < 1024) {
                        __half2 h = __floats2half2_rn(v0, v1);
                        *(__half2*)&g_k[(size_t)row * 1024 + col0] = h;
                    } else {
                        int ff = col0 - 1024;
                        int h_ = ff >> 6, d = ff & 63;
                        int sI = row >> 2, bI = row & 3;
                        size_t base = (size_t)(((bI << 4) + h_) * 64 + d) * 1024 + sI;
                        g_vth[base] = __float2half_rn(v0);
                        g_vth[base + 1024] = __float2half_rn(v1);
                    }
                } else if constexpr (MODE == 3) {
                    float2 o = {v0 + bias[col0], v1 + bias[col0 + 1]};
                    *(float2*)&Cout[(size_t)row * 1024 + col0] = o;
                } else {
                    __half2 h = __floats2half2_rn(v0, v1);
                    *(__half2*)&g_ctx2[(size_t)(row * 4 + bq) * 1024 + fq + col0] = h;
                }
            }
        }
    }
}

// ============================================================================
// Scores GEMM fp16: per (s-blk, t-blk, z): 128x128 tile, K=64, one smem load.
// 8 warps (4m x 2n), warp tile 32x64. Raw f32 scores -> g_sc.
// ============================================================================
__global__ __launch_bounds__(256)
void scores_gemm()
{
    __shared__ __align__(16) __half As[128 * 72];
    __shared__ __align__(16) __half Bs[128 * 72];

    const int tid = threadIdx.x;
    const int wid = tid >> 5, lane = tid & 31;
    const int wm = wid & 3, wn = wid >> 2;
    const int g = lane >> 2, t4 = lane & 3;
    const int s0b = blockIdx.x * 128;
    const int t0 = blockIdx.y * 128;
    const int z = blockIdx.z;
    const int b = z >> 4;
    const int fq = (z & 15) * 64;

    #pragma unroll
    for (int r = 0; r < 4; r++) {
        int idx = tid + r * 256;
        int row = idx >> 3, c8 = (idx & 7) * 8;
        uint4 ua = *(const uint4*)(g_q + (size_t)((t0 + row) * 4 + b) * 1024 + fq + c8);
        *(uint4*)&As[row * 72 + c8] = ua;
        uint4 ub = *(const uint4*)(g_k + (size_t)((s0b + row) * 4 + b) * 1024 + fq + c8);
        *(uint4*)&Bs[row * 72 + c8] = ub;
    }
    __syncthreads();

    float c[2][8][4];
    #pragma unroll
    for (int mi = 0; mi < 2; mi++)
        #pragma unroll
        for (int ni = 0; ni < 8; ni++)
            #pragma unroll
            for (int e = 0; e < 4; e++) c[mi][ni][e] = 0.f;

    #pragma unroll
    for (int step = 0; step < 4; step++) {
        const int kb = step * 16 + t4 * 2;
        uint32_t a[2][4], bfr[8][2];
        #pragma unroll
        for (int mi = 0; mi < 2; mi++) {
            int r = (wm * 32 + mi * 16 + g) * 72;
            a[mi][0] = *(const uint32_t*)&As[r + kb];
            a[mi][1] = *(const uint32_t*)&As[r + 576 + kb];
            a[mi][2] = *(const uint32_t*)&As[r + kb + 8];
            a[mi][3] = *(const uint32_t*)&As[r + 576 + kb + 8];
        }
        #pragma unroll
        for (int ni = 0; ni < 8; ni++) {
            int rn = (wn * 64 + ni * 8 + g) * 72;
            bfr[ni][0] = *(const uint32_t*)&Bs[rn + kb];
            bfr[ni][1] = *(const uint32_t*)&Bs[rn + kb + 8];
        }
        #pragma unroll
        for (int mi = 0; mi < 2; mi++)
            #pragma unroll
            for (int ni = 0; ni < 8; ni++)
                mma16n8k16(c[mi][ni], a[mi], bfr[ni]);
    }

    float* out = g_sc + (size_t)z * (1024 * 1024);
    #pragma unroll
    for (int mi = 0; mi < 2; mi++) {
        #pragma unroll
        for (int ni = 0; ni < 8; ni++) {
            int r0 = t0 + wm * 32 + mi * 16 + g;
            int col0 = s0b + wn * 64 + ni * 8 + t4 * 2;
            float2 o0 = {c[mi][ni][0], c[mi][ni][1]};
            float2 o1 = {c[mi][ni][2], c[mi][ni][3]};
            *(float2*)&out[(size_t)r0 * 1024 + col0] = o0;
            *(float2*)&out[(size_t)(r0 + 8) * 1024 + col0] = o1;
        }
    }
}

// ============================================================================
// Softmax + mask + avg, block per (b,t): 16 warps = 16 heads, row in regs.
// probs -> g_sch (fp16); block-reduce over smem staging -> avg output.
// ============================================================================
__global__ __launch_bounds__(512)
void softmax_avg(const float* __restrict__ mask, float* __restrict__ avg_out)
{
    __shared__ __half st[16][1024];

    const int bt = blockIdx.x;              // b*1024 + t
    const int b = bt >> 10, t = bt & 1023;
    const int tid = threadIdx.x;
    const int wid = tid >> 5, lane = tid & 31;
    const int z = b * 16 + wid;

    const float4* rp = (const float4*)(g_sc + ((size_t)z * 1024 + t) * 1024) + lane;
    float4 x[8];
    #pragma unroll
    for (int i = 0; i < 8; i++) x[i] = rp[i * 32];

    float mx = -1e30f;
    #pragma unroll
    for (int i = 0; i < 8; i++)
        mx = fmaxf(mx, fmaxf(fmaxf(x[i].x, x[i].y), fmaxf(x[i].z, x[i].w)));
    #pragma unroll
    for (int o = 16; o >= 1; o >>= 1)
        mx = fmaxf(mx, __shfl_xor_sync(0xffffffffu, mx, o));

    float sum = 0.f;
    #pragma unroll
    for (int i = 0; i < 8; i++) {
        x[i].x = __expf(x[i].x - mx);
        x[i].y = __expf(x[i].y - mx);
        x[i].z = __expf(x[i].z - mx);
        x[i].w = __expf(x[i].w - mx);
        sum += (x[i].x + x[i].y) + (x[i].z + x[i].w);
    }
    #pragma unroll
    for (int o = 16; o >= 1; o >>= 1)
        sum += __shfl_xor_sync(0xffffffffu, sum, o);
    const float inv = 1.f / sum;

    const float4* mrow = (const float4*)(mask + (size_t)bt * 1024) + lane;
    __half* prow = g_sch + ((size_t)z * 1024 + t) * 1024;
    #pragma unroll
    for (int i = 0; i < 8; i++) {
        float4 mk = mrow[i * 32];
        float p0 = x[i].x * inv * mk.x;
        float p1 = x[i].y * inv * mk.y;
        float p2 = x[i].z * inv * mk.z;
        float p3 = x[i].w * inv * mk.w;
        __half2 q0 = __floats2half2_rn(p0, p1);
        __half2 q1 = __floats2half2_rn(p2, p3);
        uint2 u = make_uint2(*(const uint32_t*)&q0, *(const uint32_t*)&q1);
        int coff = lane * 4 + 128 * i;
        *(uint2*)&prow[coff] = u;
        *(uint2*)&st[wid][coff] = u;
    }
    __syncthreads();

    float s0 = 0.f, s1 = 0.f;
    #pragma unroll
    for (int h = 0; h < 16; h++) {
        __half2 hv = *(const __half2*)&st[h][tid * 2];
        float2 f = __half22float2(hv);
        s0 += f.x; s1 += f.y;
    }
    float2 o = {s0 * 0.0625f, s1 * 0.0625f};
    *(float2*)&avg_out[(size_t)bt * 1024 + tid * 2] = o;
}

// ---------------------------------------------------------------------------
extern "C" void kernel_launch(void* const* d_in, const int* in_sizes, int n_in,
                              void* d_out, int out_size)
{
    const float* query = (const float*)d_in[0];
    const float* key   = (const float*)d_in[1];
    const float* mask  = (const float*)d_in[2];
    const float* w_in  = (const float*)d_in[3];
    const float* b_in  = (const float*)d_in[4];
    const float* w_out = (const float*)d_in[5];
    const float* b_out = (const float*)d_in[6];
    float* out = (float*)d_out;                         // [t][b][e]
    float* avg = out + (size_t)T_LEN * BSZ * EMB;       // [b][t][s]

    __half* d_qf;  cudaGetSymbolAddress((void**)&d_qf,  g_qf);
    __half* d_kf;  cudaGetSymbolAddress((void**)&d_kf,  g_kf);
    __half* d_wi;  cudaGetSymbolAddress((void**)&d_wi,  g_wi);
    __half* d_wo;  cudaGetSymbolAddress((void**)&d_wo,  g_wo);

    // 0) fp32 -> fp16 conversions (12M elements total)
    cvt_f2h<<<4096, 256>>>(query, d_qf, 1024 * 1024);
    cvt_f2h<<<4096, 256>>>(key,   d_kf, 1024 * 1024);
    cvt_f2h<<<3072, 256>>>(w_in,  d_wi, 3 * 256 * 1024);
    cvt_f2h<<<1024, 256>>>(w_out, d_wo, 256 * 1024);

    // 1) Q projection -> g_q fp16 (scaled)
    gemm_h<0, 128><<<dim3(8, 32), 256>>>(b_in, nullptr);
    // 2) KV projection -> g_k fp16, g_vth fp16 (V transposed)
    gemm_h<1, 128><<<dim3(16, 32), 256>>>(b_in + EMB, nullptr);
    // 3) scores (raw f32) -> g_sc
    scores_gemm<<<dim3(8, 8, 64), 256>>>();
    // 4) softmax + mask + avg -> g_sch (fp16 probs), avg output
    softmax_avg<<<4096, 512>>>(mask, avg);
    // 5) PV -> g_ctx2 fp16 ([t,b,e])
    gemm_h<4, 64><<<dim3(8, 64), 256>>>(nullptr, nullptr);
    // 6) output projection -> d_out (f32)
    gemm_h<3, 128><<<dim3(8, 32), 256>>>(b_out, out);
}